// round 9
// baseline (speedup 1.0000x reference)
#include <cuda_runtime.h>
#include <math.h>

#define NB 2
#define NC 14
#define NCLS 13          // classes 1..13
#define NPAIR (NB*NCLS)  // 26
#define NCTA 148
#define NTHR 512
#define NLBL (2*NB*16384)   // 65536 pixel-slots (student+teacher)
#define BIGD 70000
#define INFV 40000          // INF marker == padding value
// gT: row-major [144 rows][130 cols] u16; rows 0..7 and 136..143 = padding
#define GROWS 144
#define GCOLS 130
#define GPAD 8

// per-(src,b,cls) seg bitmaps, 512 words each
__device__ unsigned g_seg[2 * NB * NCLS * 512];
// per-(b,cls) student logit>0.5 bitmaps
__device__ unsigned g_gt05[NB * NCLS * 512];
__device__ float g_part[NPAIR * 4];
__device__ int   g_counter = 0;   // finish counter (self-resetting)
__device__ int   g_cnt     = 0;   // barrier ticket counter (self-resetting)
__device__ int   g_release = 0;   // barrier sense flag (flips each launch)

__global__ void __launch_bounds__(NTHR, 1)
fused_kernel(const float* __restrict__ stud,
             const float* __restrict__ teach,
             float* __restrict__ out) {
    extern __shared__ unsigned char smem[];
    // [0,37440)        gT row-major u16 (incl. padding rows)
    // [37440,39488)    Sm seed bitmap (512 u32)
    // [39488,72256)    list (u16 x 16384); early alias: segS/segT/g05 (6 KB)
    unsigned short* gT   = (unsigned short*)smem;
    unsigned*       Sm   = (unsigned*)(smem + 37440);
    unsigned short* list = (unsigned short*)(smem + 39488);
    unsigned*       segS = (unsigned*)(smem + 39488);
    unsigned*       segT = segS + 512;
    unsigned*       g05  = segT + 512;
    __shared__ float s_warp[16];
    __shared__ int   s_wsum[16];

    int t   = threadIdx.x;
    int bid = blockIdx.x;

    // read barrier sense BEFORE any arrival can flip it
    int my_sense = 0;
    if (t == 0) my_sense = *(volatile int*)&g_release;

    // ---- Stage A: argmax + direct bitmap emission via ballots ----
    int gid = bid * NTHR + t;
    if (gid < NLBL) {                        // warp-aligned boundary
        int src = gid >> 15;
        int rem = gid & 32767;               // b*16384 + pix
        int b   = rem >> 14;
        int pix = rem & 16383;
        const float* base = (src ? teach : stud) +
                            (size_t)b * NC * 16384 + pix;
        float v[NC];
#pragma unroll
        for (int c = 0; c < NC; c++) v[c] = base[(size_t)c * 16384];
        float best = v[0];
        int bi = 0;
#pragma unroll
        for (int c = 1; c < NC; c++)
            if (v[c] > best) { best = v[c]; bi = c; }

        int word = pix >> 5;
        int lane0 = ((t & 31) == 0);
        unsigned* segbase = g_seg + (size_t)((src * NB + b) * NCLS) * 512 + word;
#pragma unroll
        for (int c = 1; c < NC; c++) {
            unsigned m = __ballot_sync(0xffffffffu, bi == c);
            if (lane0) segbase[(c - 1) * 512] = m;
        }
        if (src == 0) {                      // student: logit>0.5 bitmaps
            unsigned* gbase = g_gt05 + (size_t)(b * NCLS) * 512 + word;
#pragma unroll
            for (int c = 1; c < NC; c++) {
                unsigned m = __ballot_sync(0xffffffffu, v[c] > 0.5f);
                if (lane0) gbase[(c - 1) * 512] = m;
            }
        }
    }

    // ---- grid-wide sense-reversing barrier (148 co-resident CTAs) ----
    __threadfence();
    __syncthreads();
    if (t == 0) {
        __threadfence();
        int ticket = atomicAdd(&g_cnt, 1);
        if (ticket == NCTA - 1) {
            g_cnt = 0;
            __threadfence();
            atomicExch(&g_release, my_sense ^ 1);
        } else {
            while (*(volatile int*)&g_release == my_sense) __nanosleep(32);
        }
        __threadfence();
    }
    __syncthreads();

    if (bid >= NPAIR * 4) return;            // 44 helper CTAs done

    // ---- Stage B: one CTA per (pair, pass) ----
    int pair = bid >> 2;
    int pass = bid & 3;
    int b    = pair / NCLS;
    int cls  = 1 + (pair % NCLS);

    // load the three bitmaps (1 word per thread)
    segS[t] = g_seg[(size_t)((0 * NB + b) * NCLS + cls - 1) * 512 + t];
    segT[t] = g_seg[(size_t)((1 * NB + b) * NCLS + cls - 1) * 512 + t];
    g05[t]  = g_gt05[(size_t)(b * NCLS + cls - 1) * 512 + t];

    // fill gT padding rows with INFV (u32-packed), concurrent with loads
    {
        unsigned* p32 = (unsigned*)gT;
        const unsigned fillv = INFV | (INFV << 16);
        // top rows [0,8): u32 [0, 8*65); bottom rows [136,144): [136*65,144*65)
        if (t < 520) p32[t] = fillv;
        int bi2 = t + (136 * 65 - 512);
        if (t >= 512 - 8 || true) { /* keep simple: second region below */ }
        if (t < 520) p32[136 * 65 + t] = fillv;
    }
    __syncthreads();

    // word-parallel erosion: word t = (row t>>2, quarter t&3)
    int row = t >> 2, w = t & 3;
    unsigned ew, tw;
    {
        unsigned cs = segS[t];
        unsigned up = (row > 0)   ? segS[t - 4] : 0u;
        unsigned dn = (row < 127) ? segS[t + 4] : 0u;
        unsigned lf = (cs << 1) | (w > 0 ? (segS[t - 1] >> 31) : 0u);
        unsigned rg = (cs >> 1) | (w < 3 ? (segS[t + 1] << 31) : 0u);
        ew = cs & ~(cs & up & dn & lf & rg);

        unsigned ct = segT[t];
        unsigned u2 = (row > 0)   ? segT[t - 4] : 0u;
        unsigned d2 = (row < 127) ? segT[t + 4] : 0u;
        unsigned l2 = (ct << 1) | (w > 0 ? (segT[t - 1] >> 31) : 0u);
        unsigned r2 = (ct >> 1) | (w < 3 ? (segT[t + 1] << 31) : 0u);
        tw = ct & ~(ct & u2 & d2 & l2 & r2);
    }

    // seed bitmap for this pass (all-register)
    // pass 0: fgP = es & gt05   pass 1: ~fgP   pass 2: et   pass 3: ~et
    unsigned inv = (pass & 1) ? 0xffffffffu : 0u;
    unsigned sv  = ((pass < 2) ? (ew & g05[t]) : tw) ^ inv;
    Sm[t] = sv;
    // barrier: after this, seg/g05 region is dead -> list may overwrite
    int any = __syncthreads_or(sv != 0u);

    int jbase = w * 32;
    const float* lgb = stud + (size_t)(b * NC + cls) * 16384;

    // ---- Compaction: deterministic list of pixels where diff2 != 0 ----
    int n_tot;
    {
        unsigned m = ew | tw;
        int cnt = __popc(m);
        int lane = t & 31, wid = t >> 5;
        int pre = cnt;
#pragma unroll
        for (int o = 1; o < 32; o <<= 1) {
            int v = __shfl_up_sync(0xffffffffu, pre, o);
            if (lane >= o) pre += v;
        }
        if (lane == 31) s_wsum[wid] = pre;
        __syncthreads();
        int wbase = 0;
        for (int k = 0; k < wid; k++) wbase += s_wsum[k];
        n_tot = 0;
#pragma unroll
        for (int k = 0; k < 16; k++) n_tot += s_wsum[k];
        int ofs = wbase + pre - cnt;
        while (m) {
            int bit = __ffs(m) - 1;
            m &= m - 1;
            int j = jbase + bit;
            list[ofs++] = (unsigned short)(((unsigned)row << 9) |
                                           ((unsigned)j << 2)   |
                                           ((ew >> bit) & 1u)   |
                                           (((tw >> bit) & 1u) << 1));
        }
    }

    // ---- Phase 1: horizontal 1D nearest-seed distance, packed u32 stores ----
    {
        int ri = t & 127;
        int qd = t >> 7;
        unsigned W[4];
#pragma unroll
        for (int k = 0; k < 4; k++) W[k] = Sm[ri * 4 + k];
        unsigned Wq = W[qd];
        int lpos = -100000;
        for (int k = qd - 1; k >= 0; k--)
            if (W[k]) { lpos = 32 * k + (31 - __clz(W[k])); break; }
        int rpos = 100000;
        for (int k = qd + 1; k < 4; k++)
            if (W[k]) { rpos = 32 * k + (__ffs(W[k]) - 1); break; }

        int jb = qd * 32;
        unsigned* dst = (unsigned*)(gT + (ri + GPAD) * GCOLS + jb);
#pragma unroll
        for (int p = 0; p < 16; p++) {
            unsigned sq2[2];
#pragma unroll
            for (int h = 0; h < 2; h++) {
                int jj = 2 * p + h;
                int j  = jb + jj;
                unsigned mL = Wq & (0xFFFFFFFFu >> (31 - jj));
                unsigned mR = Wq >> jj;
                int dl = mL ? (jj - (31 - __clz(mL))) : (j - lpos);
                int dr = mR ? (__ffs(mR) - 1)         : (rpos - j);
                int d  = min(dl, dr);
                sq2[h] = (d > 127) ? (unsigned)INFV : (unsigned)(d * d);
            }
            dst[p] = sq2[0] | (sq2[1] << 16);
        }
    }
    __syncthreads();   // list + gT complete

    // ---- Phase 2: fixed-radius (R=8) unrolled search + rare fallback ----
    float acc = 0.f;
    if (any) {
        float fcls = (float)cls;
        for (int k = t; k < n_tot; k += NTHR) {
            unsigned e = list[k];
            int i = e >> 9;
            int j = (e >> 2) & 127;
            float pred = (e & 1u) ? lgb[i * 128 + j] : 0.f;   // issued early
            float targ = (e & 2u) ? fcls : 0.f;
            const unsigned short* g = gT + (i + GPAD) * GCOLS + j;
            int best = g[0];
            int c1 = min((int)g[ 1 * GCOLS], (int)g[-1 * GCOLS]) + 1;
            int c2 = min((int)g[ 2 * GCOLS], (int)g[-2 * GCOLS]) + 4;
            int c3 = min((int)g[ 3 * GCOLS], (int)g[-3 * GCOLS]) + 9;
            int c4 = min((int)g[ 4 * GCOLS], (int)g[-4 * GCOLS]) + 16;
            int c5 = min((int)g[ 5 * GCOLS], (int)g[-5 * GCOLS]) + 25;
            int c6 = min((int)g[ 6 * GCOLS], (int)g[-6 * GCOLS]) + 36;
            int c7 = min((int)g[ 7 * GCOLS], (int)g[-7 * GCOLS]) + 49;
            int c8 = min((int)g[ 8 * GCOLS], (int)g[-8 * GCOLS]) + 64;
            best = min(best, min(min(min(c1, c2), min(c3, c4)),
                                 min(min(c5, c6), min(c7, c8))));
            if (best > 64) {   // rare exact fallback beyond R=8
#pragma unroll 1
                for (int r = 9; r * r < best; r++) {
                    int lo = (r <= i + GPAD)        ? (int)g[-r * GCOLS] : BIGD;
                    int hi = (i + r < 128 + GPAD)   ? (int)g[ r * GCOLS] : BIGD;
                    best = min(best, min(lo, hi) + r * r);
                }
            }
            float dt2 = (best < INFV) ? (float)best : 0.f;
            float d = pred - targ;
            acc += d * d * dt2;
        }
    }

    // warp-shuffle reduction
#pragma unroll
    for (int o = 16; o; o >>= 1) acc += __shfl_down_sync(0xffffffffu, acc, o);
    if ((t & 31) == 0) s_warp[t >> 5] = acc;
    __syncthreads();

    // ---- finish: last CTA's warp 0 does the parallel log-combine ----
    if (t < 32) {
        if (t == 0) {
            float tot = 0.f;
#pragma unroll
            for (int k = 0; k < 16; k++) tot += s_warp[k];
            g_part[bid] = tot;
            __threadfence();
        }
        int last = 0;
        if (t == 0) last = (atomicAdd(&g_counter, 1) == NPAIR * 4 - 1);
        last = __shfl_sync(0xffffffffu, last, 0);
        if (last) {
            __threadfence();
            float v = 0.f;
            if (t < NPAIR) {
                volatile float* vp = g_part;
                float hd = (vp[4 * t + 0] + vp[4 * t + 1] +
                            vp[4 * t + 2] + vp[4 * t + 3]) * (1.f / 16384.f);
                v = logf(hd + 1.f);
            }
#pragma unroll
            for (int o = 16; o; o >>= 1)
                v += __shfl_down_sync(0xffffffffu, v, o);
            if (t == 0) {
                out[0] = 0.5f * v;   // (1 - LOSS_WEIGHT) * sum
                g_counter = 0;       // self-reset -> deterministic replays
            }
        }
    }
}

extern "C" void kernel_launch(void* const* d_in, const int* in_sizes, int n_in,
                              void* d_out, int out_size) {
    const float* stud  = (const float*)d_in[0];
    const float* teach = (const float*)d_in[1];
    float* out = (float*)d_out;

    const int SMEM = 37440 + 2048 + 32768;   // 72256 B dynamic
    cudaFuncSetAttribute(fused_kernel,
                         cudaFuncAttributeMaxDynamicSharedMemorySize, SMEM);
    fused_kernel<<<NCTA, NTHR, SMEM>>>(stud, teach, out);
}